// round 14
// baseline (speedup 1.0000x reference)
#include <cuda_runtime.h>

// MS-SSIM loss, 4 scales. v13: ONE merged launch.
//  Blocks 0..12287: scale-0 tiles (SSIM + pool -> g_p1; publish per-plane
//  counter AFTER the g_acc update). Blocks 12288..16319: scales 1+2+3
//  (independent given g_p1; each spins on its plane's counter). Last B block
//  finalizes the loss and resets all state (graph-replay safe).
// Math: f32x2 sum/diff form (s=a+b, d=a-b; conv (s,d) and (s^2,d^2)).

#define NPLANES 48
typedef unsigned long long ull;

// ---- device globals (no allocations allowed; zero-init at load) ----
__device__ float  g_acc[4];
__device__ int    g_adone[NPLANES];   // s0 tiles completed per plane
__device__ int    g_fdone;            // completed B blocks
__device__ float2 g_p1[48 * 256 * 256];

// ---- packed f32x2 helpers ----
__device__ __forceinline__ ull pack2(float lo, float hi) {
    ull r;
    asm("mov.b64 %0, {%1, %2};" : "=l"(r) : "f"(lo), "f"(hi));
    return r;
}
__device__ __forceinline__ void unpack2(ull v, float& lo, float& hi) {
    asm("mov.b64 {%0, %1}, %2;" : "=f"(lo), "=f"(hi) : "l"(v));
}
__device__ __forceinline__ void ffma2(ull& acc, ull a, ull b) {
    asm("fma.rn.f32x2 %0, %1, %2, %0;" : "+l"(acc) : "l"(a), "l"(b));
}
__device__ __forceinline__ ull fmul2(ull a, ull b) {
    ull d;
    asm("mul.rn.f32x2 %0, %1, %2;" : "=l"(d) : "l"(a), "l"(b));
    return d;
}
__device__ __forceinline__ int ld_acquire(const int* p) {
    int v;
    asm volatile("ld.acquire.gpu.global.b32 %0, [%1];" : "=r"(v) : "l"(p) : "memory");
    return v;
}

// Gaussian(11, sigma=1.5), normalized.
#define G_LIST { \
    0.00102838f, 0.00759875f, 0.03600077f, 0.10936070f, 0.21300553f, \
    0.26601172f, \
    0.21300553f, 0.10936070f, 0.03600077f, 0.00759875f, 0.00102838f }

// Unified tile config: 32x32 outputs, 256 threads, RPT=4.
#define TW 32
#define TH 32
#define RPT 4
#define NT 256
#define IH 42
#define LP 50                 // sSD pitch (row 400B: quad-rotating banks)
#define SLOTS 4
#define NGRP (IH * SLOTS)     // 168 H-pass groups
#define HP 33                 // h12 pitch (row 528B: quad-rotating banks)

#define A_TOT 12288           // 16x16 tiles x 48 planes (scale 0)
#define B_S1 3072
#define B_S2 768
#define B_S3 192
#define B_TOT (B_S1 + B_S2 + B_S3)   // 4032
#define ALL_TOT (A_TOT + B_TOT)      // 16320

// ---- one 8-wide H-pass group (two 5-load phases) ----
__device__ __forceinline__ void h_group(
    float2 (*sSD)[LP], ulonglong2 (*h12)[HP], const ull* g2, int i)
{
    int r  = i % IH;               // row-fastest: conflict-free LDS phases
    int sl = i / IH;
    int c0 = 8 * sl;
    ull a1[8], a2[8];
    #pragma unroll
    for (int j = 0; j < 8; j++) { a1[j] = 0ull; a2[j] = 0ull; }
    {
        ull w[10];                 // cols c0+2 .. c0+11
        #pragma unroll
        for (int q = 0; q < 5; q++) {
            ulonglong2 u = *reinterpret_cast<const ulonglong2*>(&sSD[r][c0 + 2 + 2 * q]);
            w[2 * q] = u.x; w[2 * q + 1] = u.y;
        }
        #pragma unroll
        for (int m = 0; m < 9; m++) {
            ull v  = w[m + 1];
            ull v2 = fmul2(v, v);
            #pragma unroll
            for (int j = 0; j < 8; j++) {
                int k = m - j;
                if (k >= 0 && k < 11) {
                    ffma2(a1[j], v,  g2[k]);
                    ffma2(a2[j], v2, g2[k]);
                }
            }
        }
    }
    {
        ull w[10];                 // cols c0+12 .. c0+21
        #pragma unroll
        for (int q = 0; q < 5; q++) {
            ulonglong2 u = *reinterpret_cast<const ulonglong2*>(&sSD[r][c0 + 12 + 2 * q]);
            w[2 * q] = u.x; w[2 * q + 1] = u.y;
        }
        #pragma unroll
        for (int m = 9; m < 18; m++) {
            ull v  = w[m - 9];
            ull v2 = fmul2(v, v);
            #pragma unroll
            for (int j = 0; j < 8; j++) {
                int k = m - j;
                if (k >= 0 && k < 11) {
                    ffma2(a1[j], v,  g2[k]);
                    ffma2(a2[j], v2, g2[k]);
                }
            }
        }
    }
    #pragma unroll
    for (int j = 0; j < 8; j++) {
        h12[r][c0 + j] = make_ulonglong2(a1[j], a2[j]);
    }
}

// ---- V-pass + SSIM + block reduce; returns block sum on tid 0 ----
__device__ __forceinline__ float v_pass_reduce(
    ulonglong2 (*h12)[HP], float* red, const ull* g2)
{
    const int tid = threadIdx.x;
    float acc = 0.0f;
    {
        const int c  = tid % TW;
        const int r0 = (tid / TW) * RPT;
        ull s1[RPT], s2[RPT];
        #pragma unroll
        for (int j = 0; j < RPT; j++) { s1[j] = 0ull; s2[j] = 0ull; }
        #pragma unroll
        for (int t = 0; t < RPT + 10; t++) {
            ulonglong2 v = h12[r0 + t][c];
            #pragma unroll
            for (int j = 0; j < RPT; j++) {
                int k = t - j;
                if (k >= 0 && k < 11) {
                    ffma2(s1[j], v.x, g2[k]);
                    ffma2(s2[j], v.y, g2[k]);
                }
            }
        }
        const float C1 = 1e-4f;
        const float C2 = 9e-4f;
        #pragma unroll
        for (int j = 0; j < RPT; j++) {
            float mus, mud, es2, ed2;
            unpack2(s1[j], mus, mud);
            unpack2(s2[j], es2, ed2);
            float Aq = mus * mus;
            float Bq = mud * mud;
            float mu12  = 0.25f * (Aq - Bq);
            float musq  = 0.5f  * (Aq + Bq);
            float sigs  = 0.5f  * (es2 + ed2) - musq;
            float sig12 = 0.25f * (es2 - ed2) - mu12;
            float num = (2.0f * mu12 + C1) * (2.0f * sig12 + C2);
            float den = (musq + C1) * (sigs + C2);
            acc += __fdividef(num, den);
        }
    }
    #pragma unroll
    for (int o = 16; o > 0; o >>= 1)
        acc += __shfl_down_sync(0xffffffffu, acc, o);
    if ((tid & 31) == 0) red[tid >> 5] = acc;
    __syncthreads();
    float s = 0.f;
    if (tid == 0) {
        #pragma unroll
        for (int w = 0; w < NT / 32; w++) s += red[w];
    }
    return s;
}

__global__ void __launch_bounds__(NT, 5)
ssim_all(const float* __restrict__ A0, const float* __restrict__ B0,
         float* __restrict__ out)
{
    __shared__ __align__(16) float2 sSD[IH][LP];
    __shared__ __align__(16) ulonglong2 h12[IH][HP];
    __shared__ float red[NT / 32];

    const float G[11] = G_LIST;
    ull g2[11];
    #pragma unroll
    for (int k = 0; k < 11; k++) g2[k] = pack2(G[k], G[k]);

    const int bid = blockIdx.x;
    const int tid = threadIdx.x;

    if (bid < A_TOT) {
        // ================= scale 0 =================
        const int plane = bid >> 8;
        const int rem   = bid & 255;
        const int ty = (rem >> 4) * TH;
        const int tx = (rem & 15) * TW;
        const int W = 512, H = 512;
        const size_t pbase = (size_t)plane * W * H;

        // stage 1: division-free map (12 float4-slots/row, stride-16 rows)
        {
            const int s  = tid & 15;      // slot (active if < 12)
            const int r0 = tid >> 4;      // 0..15
            if (s < 12) {
                for (int r = r0; r < IH; r += 16) {
                    int gy = ty + r - 5;
                    int gx = tx + 4 * s - 8;
                    float4 a = make_float4(0.f, 0.f, 0.f, 0.f);
                    float4 b = a;
                    if ((unsigned)gy < (unsigned)H && (unsigned)gx <= (unsigned)(W - 4)) {
                        size_t idx = pbase + (size_t)gy * W + gx;
                        a = *reinterpret_cast<const float4*>(A0 + idx);
                        b = *reinterpret_cast<const float4*>(B0 + idx);
                    }
                    float4 lo = make_float4(a.x + b.x, a.x - b.x, a.y + b.y, a.y - b.y);
                    float4 hi = make_float4(a.z + b.z, a.z - b.z, a.w + b.w, a.w - b.w);
                    *reinterpret_cast<float4*>(&sSD[r][4 * s])     = lo;
                    *reinterpret_cast<float4*>(&sSD[r][4 * s + 2]) = hi;
                }
            }
        }
        __syncthreads();

        // stage 2 (threads < NGRP) concurrent with pool (threads >= NGRP)
        if (tid < NGRP) {
            h_group(sSD, h12, g2, tid);
        } else {
            for (int i = tid - NGRP; i < 256; i += NT - NGRP) {
                int pr = i >> 4;
                int pc = i & 15;
                int r = 5 + 2 * pr;
                int c = 8 + 2 * pc;
                float2 q00 = sSD[r][c],     q01 = sSD[r][c + 1];
                float2 q10 = sSD[r + 1][c], q11 = sSD[r + 1][c + 1];
                float2 o;
                o.x = 0.25f * (q00.x + q01.x + q10.x + q11.x);
                o.y = 0.25f * (q00.y + q01.y + q10.y + q11.y);
                size_t pidx = (size_t)plane * 256 * 256
                            + (size_t)((ty >> 1) + pr) * 256 + ((tx >> 1) + pc);
                g_p1[pidx] = o;
            }
            __threadfence();   // writer-side fence: g_p1 visible gpu-wide
        }
        __syncthreads();

        float s = v_pass_reduce(h12, red, g2);
        if (tid == 0) {
            atomicAdd(&g_acc[0], s);
            __threadfence();                      // acc + p1 before counter
            atomicAdd(&g_adone[plane], 1);
        }
        return;
    }

    // ================= scales 1+2+3 =================
    const int bb = bid - A_TOT;
    int scale, plane, txi, tyi, W;
    if (bb < B_S1) {
        scale = 1; W = 256;
        plane = bb >> 6; int rem = bb & 63; tyi = rem >> 3; txi = rem & 7;
    } else if (bb < B_S1 + B_S2) {
        int r = bb - B_S1;
        scale = 2; W = 128;
        plane = r >> 4; int rem = r & 15; tyi = rem >> 2; txi = rem & 3;
    } else {
        int r = bb - (B_S1 + B_S2);
        scale = 3; W = 64;
        plane = r >> 2; int rem = r & 3; tyi = rem >> 1; txi = rem & 1;
    }
    const int H = W;
    const int tx = txi * TW;
    const int ty = tyi * TH;
    const size_t p1base = (size_t)plane * 256 * 256;
    const float2* __restrict__ P1 = g_p1;

    // wait for this plane's scale-0 output (g_p1)
    if (tid == 0) {
        int ns = 64;
        while (ld_acquire(&g_adone[plane]) < 256) {
            __nanosleep(ns);
            if (ns < 4096) ns <<= 1;
        }
    }
    __syncthreads();

    // ---- stage 1: build the scale-s (s,d) tile from g_p1 ----
    if (scale == 1) {
        const int s  = tid & 31;      // float4 slot (2px), active if < 24
        const int r0 = tid >> 5;      // 0..7
        if (s < 24) {
            for (int r = r0; r < IH; r += 8) {
                int gy = ty + r - 5;
                int gx = tx + 2 * s - 8;
                float4 v = make_float4(0.f, 0.f, 0.f, 0.f);
                if ((unsigned)gy < 256u && (unsigned)gx <= 254u) {
                    v = *reinterpret_cast<const float4*>(P1 + p1base + (size_t)gy * 256 + gx);
                }
                *reinterpret_cast<float4*>(&sSD[r][2 * s]) = v;
            }
        }
    } else if (scale == 2) {
        const int c  = tid & 63;      // column, active if < 48
        const int r0 = tid >> 6;      // 0..3
        if (c < 48) {
            for (int r = r0; r < IH; r += 4) {
                int gy = ty + r - 5;
                int gx = tx + c - 8;
                float2 o = make_float2(0.f, 0.f);
                if ((unsigned)gy < (unsigned)H && (unsigned)gx < (unsigned)W) {
                    float4 r0v = *reinterpret_cast<const float4*>(
                        P1 + p1base + (size_t)(2 * gy) * 256 + 2 * gx);
                    float4 r1v = *reinterpret_cast<const float4*>(
                        P1 + p1base + (size_t)(2 * gy + 1) * 256 + 2 * gx);
                    o.x = 0.25f * (r0v.x + r0v.z + r1v.x + r1v.z);
                    o.y = 0.25f * (r0v.y + r0v.w + r1v.y + r1v.w);
                }
                sSD[r][c] = o;
            }
        }
    } else {
        const int c  = tid & 63;
        const int r0 = tid >> 6;
        if (c < 48) {
            for (int r = r0; r < IH; r += 4) {
                int gy = ty + r - 5;
                int gx = tx + c - 8;
                float2 o = make_float2(0.f, 0.f);
                if ((unsigned)gy < (unsigned)H && (unsigned)gx < (unsigned)W) {
                    float qx[4], qy[4];
                    #pragma unroll
                    for (int dy = 0; dy < 2; dy++) {
                        #pragma unroll
                        for (int dx = 0; dx < 2; dx++) {
                            int sy = 4 * gy + 2 * dy;
                            int sx = 4 * gx + 2 * dx;
                            float4 r0v = *reinterpret_cast<const float4*>(
                                P1 + p1base + (size_t)sy * 256 + sx);
                            float4 r1v = *reinterpret_cast<const float4*>(
                                P1 + p1base + (size_t)(sy + 1) * 256 + sx);
                            qx[2 * dy + dx] = 0.25f * (r0v.x + r0v.z + r1v.x + r1v.z);
                            qy[2 * dy + dx] = 0.25f * (r0v.y + r0v.w + r1v.y + r1v.w);
                        }
                    }
                    o.x = 0.25f * (qx[0] + qx[1] + qx[2] + qx[3]);
                    o.y = 0.25f * (qy[0] + qy[1] + qy[2] + qy[3]);
                }
                sSD[r][c] = o;
            }
        }
    }
    __syncthreads();

    if (tid < NGRP) h_group(sSD, h12, g2, tid);
    __syncthreads();

    float s = v_pass_reduce(h12, red, g2);
    if (tid == 0) {
        atomicAdd(&g_acc[scale], s);
        __threadfence();
        int d = atomicAdd(&g_fdone, 1);
        if (d == B_TOT - 1) {             // last B block: finalize + reset
            float a0 = atomicAdd(&g_acc[0], 0.0f);
            float a1 = atomicAdd(&g_acc[1], 0.0f);
            float a2 = atomicAdd(&g_acc[2], 0.0f);
            float a3 = atomicAdd(&g_acc[3], 0.0f);
            const float wgt[4] = {0.0448f, 0.2856f, 0.3001f, 0.2363f};
            float n0 = 48.0f * 512.0f * 512.0f;
            out[0] = wgt[0] * (1.0f - a0 / n0)
                   + wgt[1] * (1.0f - a1 / (n0 * 0.25f))
                   + wgt[2] * (1.0f - a2 / (n0 * 0.0625f))
                   + wgt[3] * (1.0f - a3 / (n0 * 0.015625f));
            #pragma unroll
            for (int s4 = 0; s4 < 4; s4++) g_acc[s4] = 0.0f;
            for (int p = 0; p < NPLANES; p++) g_adone[p] = 0;
            g_fdone = 0;                  // reset for next graph replay
        }
    }
}

extern "C" void kernel_launch(void* const* d_in, const int* in_sizes, int n_in,
                              void* d_out, int out_size) {
    const float* img1 = (const float*)d_in[0];
    const float* img2 = (const float*)d_in[1];
    float* out = (float*)d_out;

    ssim_all<<<ALL_TOT, NT>>>(img1, img2, out);
}

// round 15
// speedup vs baseline: 1.0319x; 1.0319x over previous
#include <cuda_runtime.h>

// MS-SSIM loss, 4 scales. v14: v12 two-launch structure (merged-launch
// spin-gating retired after 3 failures) +
//  - sSD pitch 50->46 (column origin shifted -2; banks re-verified):
//    smem 39.1->37.7KB -> 6 blocks/SM possible
//  - __launch_bounds__(256,6): reg cap 42 for 48 warps/SM
//  - division-free stage-1 thread maps
// Math: f32x2 sum/diff form (s=a+b, d=a-b; conv (s,d) and (s^2,d^2)).

#define NPLANES 48
typedef unsigned long long ull;

// ---- device globals (no allocations allowed; zero-init at load) ----
__device__ float  g_acc[4];
__device__ int    g_fdone;
__device__ float2 g_p1[48 * 256 * 256];   // scale-1 (s,d) image

// ---- packed f32x2 helpers ----
__device__ __forceinline__ ull pack2(float lo, float hi) {
    ull r;
    asm("mov.b64 %0, {%1, %2};" : "=l"(r) : "f"(lo), "f"(hi));
    return r;
}
__device__ __forceinline__ void unpack2(ull v, float& lo, float& hi) {
    asm("mov.b64 {%0, %1}, %2;" : "=f"(lo), "=f"(hi) : "l"(v));
}
__device__ __forceinline__ void ffma2(ull& acc, ull a, ull b) {
    asm("fma.rn.f32x2 %0, %1, %2, %0;" : "+l"(acc) : "l"(a), "l"(b));
}
__device__ __forceinline__ ull fmul2(ull a, ull b) {
    ull d;
    asm("mul.rn.f32x2 %0, %1, %2;" : "=l"(d) : "l"(a), "l"(b));
    return d;
}

// Gaussian(11, sigma=1.5), normalized.
#define G_LIST { \
    0.00102838f, 0.00759875f, 0.03600077f, 0.10936070f, 0.21300553f, \
    0.26601172f, \
    0.21300553f, 0.10936070f, 0.03600077f, 0.00759875f, 0.00102838f }

// Tile: 32x32 outputs, 256 threads, RPT=4.
// Column convention (v14): smem col c <-> image col gx = tx + c - 6.
// Used cols: 0..45 (output j of group c0 taps cols c0+j+1 .. c0+j+11).
#define TW 32
#define TH 32
#define RPT 4
#define NT 256
#define IH 42
#define LP 46                 // sSD pitch (row 368B: disjoint bank quads)
#define SLOTS 4
#define NGRP (IH * SLOTS)     // 168 H-pass groups
#define HP 33                 // h12 pitch (row 528B: disjoint bank quads)

#define B_S1 3072
#define B_S2 768
#define B_S3 192
#define B_TOT (B_S1 + B_S2 + B_S3)   // 4032

// ---- one 8-wide H-pass group (two 5-load phases) ----
__device__ __forceinline__ void h_group(
    float2 (*sSD)[LP], ulonglong2 (*h12)[HP], const ull* g2, int i)
{
    int r  = i % IH;               // row-fastest: conflict-free LDS phases
    int sl = i / IH;
    int c0 = 8 * sl;
    ull a1[8], a2[8];
    #pragma unroll
    for (int j = 0; j < 8; j++) { a1[j] = 0ull; a2[j] = 0ull; }
    {
        ull w[10];                 // cols c0 .. c0+9
        #pragma unroll
        for (int q = 0; q < 5; q++) {
            ulonglong2 u = *reinterpret_cast<const ulonglong2*>(&sSD[r][c0 + 2 * q]);
            w[2 * q] = u.x; w[2 * q + 1] = u.y;
        }
        #pragma unroll
        for (int m = 0; m < 9; m++) {    // tap col c0+1+m = w[m+1]
            ull v  = w[m + 1];
            ull v2 = fmul2(v, v);
            #pragma unroll
            for (int j = 0; j < 8; j++) {
                int k = m - j;
                if (k >= 0 && k < 11) {
                    ffma2(a1[j], v,  g2[k]);
                    ffma2(a2[j], v2, g2[k]);
                }
            }
        }
    }
    {
        ull w[10];                 // cols c0+10 .. c0+19
        #pragma unroll
        for (int q = 0; q < 5; q++) {
            ulonglong2 u = *reinterpret_cast<const ulonglong2*>(&sSD[r][c0 + 10 + 2 * q]);
            w[2 * q] = u.x; w[2 * q + 1] = u.y;
        }
        #pragma unroll
        for (int m = 9; m < 18; m++) {   // tap col c0+1+m = w[m-9]
            ull v  = w[m - 9];
            ull v2 = fmul2(v, v);
            #pragma unroll
            for (int j = 0; j < 8; j++) {
                int k = m - j;
                if (k >= 0 && k < 11) {
                    ffma2(a1[j], v,  g2[k]);
                    ffma2(a2[j], v2, g2[k]);
                }
            }
        }
    }
    #pragma unroll
    for (int j = 0; j < 8; j++) {
        h12[r][c0 + j] = make_ulonglong2(a1[j], a2[j]);
    }
}

// ---- V-pass + SSIM + block reduce; returns block sum on tid 0 ----
__device__ __forceinline__ float v_pass_reduce(
    ulonglong2 (*h12)[HP], float* red, const ull* g2)
{
    const int tid = threadIdx.x;
    float acc = 0.0f;
    {
        const int c  = tid & (TW - 1);
        const int r0 = (tid >> 5) * RPT;
        ull s1[RPT], s2[RPT];
        #pragma unroll
        for (int j = 0; j < RPT; j++) { s1[j] = 0ull; s2[j] = 0ull; }
        #pragma unroll
        for (int t = 0; t < RPT + 10; t++) {
            ulonglong2 v = h12[r0 + t][c];
            #pragma unroll
            for (int j = 0; j < RPT; j++) {
                int k = t - j;
                if (k >= 0 && k < 11) {
                    ffma2(s1[j], v.x, g2[k]);
                    ffma2(s2[j], v.y, g2[k]);
                }
            }
        }
        const float C1 = 1e-4f;
        const float C2 = 9e-4f;
        #pragma unroll
        for (int j = 0; j < RPT; j++) {
            float mus, mud, es2, ed2;
            unpack2(s1[j], mus, mud);
            unpack2(s2[j], es2, ed2);
            float Aq = mus * mus;
            float Bq = mud * mud;
            float mu12  = 0.25f * (Aq - Bq);
            float musq  = 0.5f  * (Aq + Bq);
            float sigs  = 0.5f  * (es2 + ed2) - musq;
            float sig12 = 0.25f * (es2 - ed2) - mu12;
            float num = (2.0f * mu12 + C1) * (2.0f * sig12 + C2);
            float den = (musq + C1) * (sigs + C2);
            acc += __fdividef(num, den);
        }
    }
    #pragma unroll
    for (int o = 16; o > 0; o >>= 1)
        acc += __shfl_down_sync(0xffffffffu, acc, o);
    if ((tid & 31) == 0) red[tid >> 5] = acc;
    __syncthreads();
    float s = 0.f;
    if (tid == 0) {
        #pragma unroll
        for (int w = 0; w < NT / 32; w++) s += red[w];
    }
    return s;
}

// ---- launch A: scale 0 (SSIM + pool -> g_p1) ----
__global__ void __launch_bounds__(NT, 6)
ssim_scale0(const float* __restrict__ A0, const float* __restrict__ B0)
{
    __shared__ __align__(16) float2 sSD[IH][LP];
    __shared__ __align__(16) ulonglong2 h12[IH][HP];
    __shared__ float red[NT / 32];

    const float G[11] = G_LIST;
    ull g2[11];
    #pragma unroll
    for (int k = 0; k < 11; k++) g2[k] = pack2(G[k], G[k]);

    const int tid   = threadIdx.x;
    const int tx    = blockIdx.x * TW;
    const int ty    = blockIdx.y * TH;
    const int plane = blockIdx.z;
    const int W = 512, H = 512;
    const size_t pbase = (size_t)plane * W * H;

    // stage 1: raw float4 (4px) loads; pixel gx+i -> smem col 4s-2+i.
    // s=0 writes only its upper pixel pair (cols 0,1); cols <0 dropped.
    {
        const int s  = tid & 15;      // slot, active if < 12
        const int r0 = tid >> 4;      // 0..15
        if (s < 12) {
            const int cb = 4 * s - 2; // col of pixel gx
            for (int r = r0; r < IH; r += 16) {
                int gy = ty + r - 5;
                int gx = tx + 4 * s - 8;
                float4 a = make_float4(0.f, 0.f, 0.f, 0.f);
                float4 b = a;
                if ((unsigned)gy < (unsigned)H && (unsigned)gx <= (unsigned)(W - 4)) {
                    size_t idx = pbase + (size_t)gy * W + gx;
                    a = *reinterpret_cast<const float4*>(A0 + idx);
                    b = *reinterpret_cast<const float4*>(B0 + idx);
                }
                float4 lo = make_float4(a.x + b.x, a.x - b.x, a.y + b.y, a.y - b.y);
                float4 hi = make_float4(a.z + b.z, a.z - b.z, a.w + b.w, a.w - b.w);
                if (cb >= 0)
                    *reinterpret_cast<float4*>(&sSD[r][cb]) = lo;
                *reinterpret_cast<float4*>(&sSD[r][cb + 2]) = hi;
            }
        }
    }
    __syncthreads();

    // stage 2 (threads < NGRP) concurrent with pool (threads >= NGRP)
    if (tid < NGRP) {
        h_group(sSD, h12, g2, tid);
    } else {
        for (int i = tid - NGRP; i < 256; i += NT - NGRP) {
            int pr = i >> 4;
            int pc = i & 15;
            int r = 5 + 2 * pr;
            int c = 6 + 2 * pc;       // gx = tx + 2*pc
            float2 q00 = sSD[r][c],     q01 = sSD[r][c + 1];
            float2 q10 = sSD[r + 1][c], q11 = sSD[r + 1][c + 1];
            float2 o;
            o.x = 0.25f * (q00.x + q01.x + q10.x + q11.x);
            o.y = 0.25f * (q00.y + q01.y + q10.y + q11.y);
            size_t pidx = (size_t)plane * 256 * 256
                        + (size_t)((ty >> 1) + pr) * 256 + ((tx >> 1) + pc);
            g_p1[pidx] = o;
        }
    }
    __syncthreads();

    float s = v_pass_reduce(h12, red, g2);
    if (tid == 0) atomicAdd(&g_acc[0], s);
}

// ---- launch B: scales 1+2+3, all independent given g_p1 ----
__global__ void __launch_bounds__(NT, 6)
ssim_small(float* __restrict__ out)
{
    __shared__ __align__(16) float2 sSD[IH][LP];
    __shared__ __align__(16) ulonglong2 h12[IH][HP];
    __shared__ float red[NT / 32];

    const float G[11] = G_LIST;
    ull g2[11];
    #pragma unroll
    for (int k = 0; k < 11; k++) g2[k] = pack2(G[k], G[k]);

    const int bid = blockIdx.x;
    const int tid = threadIdx.x;

    int scale, plane, txi, tyi, W;
    if (bid < B_S1) {
        scale = 1; W = 256;
        plane = bid >> 6; int rem = bid & 63; tyi = rem >> 3; txi = rem & 7;
    } else if (bid < B_S1 + B_S2) {
        int r = bid - B_S1;
        scale = 2; W = 128;
        plane = r >> 4; int rem = r & 15; tyi = rem >> 2; txi = rem & 3;
    } else {
        int r = bid - (B_S1 + B_S2);
        scale = 3; W = 64;
        plane = r >> 2; int rem = r & 3; tyi = rem >> 1; txi = rem & 1;
    }
    const int H = W;
    const int tx = txi * TW;
    const int ty = tyi * TH;
    const size_t p1base = (size_t)plane * 256 * 256;
    const float2* __restrict__ P1 = g_p1;

    // ---- stage 1: build the scale-s (s,d) tile (col c <-> gx = tx+c-6) ----
    if (scale == 1) {
        const int s  = tid & 31;      // float4 slot (2px), active if < 23
        const int r0 = tid >> 5;      // 0..7
        if (s < 23) {
            for (int r = r0; r < IH; r += 8) {
                int gy = ty + r - 5;
                int gx = tx + 2 * s - 6;
                float4 v = make_float4(0.f, 0.f, 0.f, 0.f);
                if ((unsigned)gy < 256u && (unsigned)gx <= 254u) {
                    v = *reinterpret_cast<const float4*>(P1 + p1base + (size_t)gy * 256 + gx);
                }
                *reinterpret_cast<float4*>(&sSD[r][2 * s]) = v;
            }
        }
    } else if (scale == 2) {
        const int c  = tid & 63;      // column, active if < 46
        const int r0 = tid >> 6;      // 0..3
        if (c < 46) {
            for (int r = r0; r < IH; r += 4) {
                int gy = ty + r - 5;
                int gx = tx + c - 6;
                float2 o = make_float2(0.f, 0.f);
                if ((unsigned)gy < (unsigned)H && (unsigned)gx < (unsigned)W) {
                    float4 r0v = *reinterpret_cast<const float4*>(
                        P1 + p1base + (size_t)(2 * gy) * 256 + 2 * gx);
                    float4 r1v = *reinterpret_cast<const float4*>(
                        P1 + p1base + (size_t)(2 * gy + 1) * 256 + 2 * gx);
                    o.x = 0.25f * (r0v.x + r0v.z + r1v.x + r1v.z);
                    o.y = 0.25f * (r0v.y + r0v.w + r1v.y + r1v.w);
                }
                sSD[r][c] = o;
            }
        }
    } else {
        const int c  = tid & 63;
        const int r0 = tid >> 6;
        if (c < 46) {
            for (int r = r0; r < IH; r += 4) {
                int gy = ty + r - 5;
                int gx = tx + c - 6;
                float2 o = make_float2(0.f, 0.f);
                if ((unsigned)gy < (unsigned)H && (unsigned)gx < (unsigned)W) {
                    float qx[4], qy[4];
                    #pragma unroll
                    for (int dy = 0; dy < 2; dy++) {
                        #pragma unroll
                        for (int dx = 0; dx < 2; dx++) {
                            int sy = 4 * gy + 2 * dy;
                            int sx = 4 * gx + 2 * dx;
                            float4 r0v = *reinterpret_cast<const float4*>(
                                P1 + p1base + (size_t)sy * 256 + sx);
                            float4 r1v = *reinterpret_cast<const float4*>(
                                P1 + p1base + (size_t)(sy + 1) * 256 + sx);
                            qx[2 * dy + dx] = 0.25f * (r0v.x + r0v.z + r1v.x + r1v.z);
                            qy[2 * dy + dx] = 0.25f * (r0v.y + r0v.w + r1v.y + r1v.w);
                        }
                    }
                    o.x = 0.25f * (qx[0] + qx[1] + qx[2] + qx[3]);
                    o.y = 0.25f * (qy[0] + qy[1] + qy[2] + qy[3]);
                }
                sSD[r][c] = o;
            }
        }
    }
    __syncthreads();

    if (tid < NGRP) h_group(sSD, h12, g2, tid);
    __syncthreads();

    float s = v_pass_reduce(h12, red, g2);
    if (tid == 0) {
        atomicAdd(&g_acc[scale], s);
        __threadfence();
        int d = atomicAdd(&g_fdone, 1);
        if (d == B_TOT - 1) {             // last block: finalize + reset
            float a0 = atomicAdd(&g_acc[0], 0.0f);
            float a1 = atomicAdd(&g_acc[1], 0.0f);
            float a2 = atomicAdd(&g_acc[2], 0.0f);
            float a3 = atomicAdd(&g_acc[3], 0.0f);
            const float wgt[4] = {0.0448f, 0.2856f, 0.3001f, 0.2363f};
            float n0 = 48.0f * 512.0f * 512.0f;
            out[0] = wgt[0] * (1.0f - a0 / n0)
                   + wgt[1] * (1.0f - a1 / (n0 * 0.25f))
                   + wgt[2] * (1.0f - a2 / (n0 * 0.0625f))
                   + wgt[3] * (1.0f - a3 / (n0 * 0.015625f));
            #pragma unroll
            for (int s4 = 0; s4 < 4; s4++) g_acc[s4] = 0.0f;
            g_fdone = 0;
        }
    }
}

extern "C" void kernel_launch(void* const* d_in, const int* in_sizes, int n_in,
                              void* d_out, int out_size) {
    const float* img1 = (const float*)d_in[0];
    const float* img2 = (const float*)d_in[1];
    float* out = (float*)d_out;

    ssim_scale0<<<dim3(16, 16, NPLANES), NT>>>(img1, img2);
    ssim_small<<<B_TOT, NT>>>(out);
}

// round 16
// speedup vs baseline: 1.1385x; 1.1033x over previous
#include <cuda_runtime.h>

// MS-SSIM loss, 4 scales. v15: exact v12 structure/config (best-known,
// 113.2us: two launches, __launch_bounds__(256,5), LP=50, no reg squeeze)
// + division-free stage-1 thread maps (the only non-implicated piece of
// v13/v14). v14's (256,6)+LP=46 caused spills (regs 40, L2 21%) -> reverted.
// Math: f32x2 sum/diff form (s=a+b, d=a-b; conv (s,d) and (s^2,d^2)).

#define NPLANES 48
typedef unsigned long long ull;

// ---- device globals (no allocations allowed; zero-init at load) ----
__device__ float  g_acc[4];
__device__ int    g_fdone;
__device__ float2 g_p1[48 * 256 * 256];   // scale-1 (s,d) image

// ---- packed f32x2 helpers ----
__device__ __forceinline__ ull pack2(float lo, float hi) {
    ull r;
    asm("mov.b64 %0, {%1, %2};" : "=l"(r) : "f"(lo), "f"(hi));
    return r;
}
__device__ __forceinline__ void unpack2(ull v, float& lo, float& hi) {
    asm("mov.b64 {%0, %1}, %2;" : "=f"(lo), "=f"(hi) : "l"(v));
}
__device__ __forceinline__ void ffma2(ull& acc, ull a, ull b) {
    asm("fma.rn.f32x2 %0, %1, %2, %0;" : "+l"(acc) : "l"(a), "l"(b));
}
__device__ __forceinline__ ull fmul2(ull a, ull b) {
    ull d;
    asm("mul.rn.f32x2 %0, %1, %2;" : "=l"(d) : "l"(a), "l"(b));
    return d;
}

// Gaussian(11, sigma=1.5), normalized.
#define G_LIST { \
    0.00102838f, 0.00759875f, 0.03600077f, 0.10936070f, 0.21300553f, \
    0.26601172f, \
    0.21300553f, 0.10936070f, 0.03600077f, 0.00759875f, 0.00102838f }

// Unified tile config: 32x32 outputs, 256 threads, RPT=4.
// Column convention (v12): smem col c <-> image col gx = tx + c - 8.
#define TW 32
#define TH 32
#define RPT 4
#define NT 256
#define IH 42
#define LP 50                 // sSD pitch (row 400B: quad-rotating banks)
#define SLOTS 4
#define NGRP (IH * SLOTS)     // 168 H-pass groups
#define HP 33                 // h12 pitch (row 528B: quad-rotating banks)

#define B_S1 3072
#define B_S2 768
#define B_S3 192
#define B_TOT (B_S1 + B_S2 + B_S3)   // 4032

// ---- one 8-wide H-pass group (two 5-load phases, bounded live regs) ----
__device__ __forceinline__ void h_group(
    float2 (*sSD)[LP], ulonglong2 (*h12)[HP], const ull* g2, int i)
{
    int r  = i % IH;               // row-fastest: conflict-free LDS phases
    int sl = i / IH;
    int c0 = 8 * sl;
    ull a1[8], a2[8];
    #pragma unroll
    for (int j = 0; j < 8; j++) { a1[j] = 0ull; a2[j] = 0ull; }
    {
        ull w[10];                 // cols c0+2 .. c0+11
        #pragma unroll
        for (int q = 0; q < 5; q++) {
            ulonglong2 u = *reinterpret_cast<const ulonglong2*>(&sSD[r][c0 + 2 + 2 * q]);
            w[2 * q] = u.x; w[2 * q + 1] = u.y;
        }
        #pragma unroll
        for (int m = 0; m < 9; m++) {    // col c0+3+m = w[m+1]
            ull v  = w[m + 1];
            ull v2 = fmul2(v, v);
            #pragma unroll
            for (int j = 0; j < 8; j++) {
                int k = m - j;
                if (k >= 0 && k < 11) {
                    ffma2(a1[j], v,  g2[k]);
                    ffma2(a2[j], v2, g2[k]);
                }
            }
        }
    }
    {
        ull w[10];                 // cols c0+12 .. c0+21
        #pragma unroll
        for (int q = 0; q < 5; q++) {
            ulonglong2 u = *reinterpret_cast<const ulonglong2*>(&sSD[r][c0 + 12 + 2 * q]);
            w[2 * q] = u.x; w[2 * q + 1] = u.y;
        }
        #pragma unroll
        for (int m = 9; m < 18; m++) {   // col c0+3+m = w[m-9]
            ull v  = w[m - 9];
            ull v2 = fmul2(v, v);
            #pragma unroll
            for (int j = 0; j < 8; j++) {
                int k = m - j;
                if (k >= 0 && k < 11) {
                    ffma2(a1[j], v,  g2[k]);
                    ffma2(a2[j], v2, g2[k]);
                }
            }
        }
    }
    #pragma unroll
    for (int j = 0; j < 8; j++) {
        h12[r][c0 + j] = make_ulonglong2(a1[j], a2[j]);
    }
}

// ---- V-pass + SSIM + block reduce; returns block sum on tid 0 ----
__device__ __forceinline__ float v_pass_reduce(
    ulonglong2 (*h12)[HP], float* red, const ull* g2)
{
    const int tid = threadIdx.x;
    float acc = 0.0f;
    {
        const int c  = tid & (TW - 1);
        const int r0 = (tid >> 5) * RPT;
        ull s1[RPT], s2[RPT];
        #pragma unroll
        for (int j = 0; j < RPT; j++) { s1[j] = 0ull; s2[j] = 0ull; }
        #pragma unroll
        for (int t = 0; t < RPT + 10; t++) {
            ulonglong2 v = h12[r0 + t][c];
            #pragma unroll
            for (int j = 0; j < RPT; j++) {
                int k = t - j;
                if (k >= 0 && k < 11) {
                    ffma2(s1[j], v.x, g2[k]);
                    ffma2(s2[j], v.y, g2[k]);
                }
            }
        }
        const float C1 = 1e-4f;
        const float C2 = 9e-4f;
        #pragma unroll
        for (int j = 0; j < RPT; j++) {
            float mus, mud, es2, ed2;
            unpack2(s1[j], mus, mud);
            unpack2(s2[j], es2, ed2);
            float Aq = mus * mus;
            float Bq = mud * mud;
            float mu12  = 0.25f * (Aq - Bq);            // mu1*mu2
            float musq  = 0.5f  * (Aq + Bq);            // mu1^2+mu2^2
            float sigs  = 0.5f  * (es2 + ed2) - musq;   // sig1^2+sig2^2
            float sig12 = 0.25f * (es2 - ed2) - mu12;   // sig12
            float num = (2.0f * mu12 + C1) * (2.0f * sig12 + C2);
            float den = (musq + C1) * (sigs + C2);
            acc += __fdividef(num, den);
        }
    }
    #pragma unroll
    for (int o = 16; o > 0; o >>= 1)
        acc += __shfl_down_sync(0xffffffffu, acc, o);
    if ((tid & 31) == 0) red[tid >> 5] = acc;
    __syncthreads();
    float s = 0.f;
    if (tid == 0) {
        #pragma unroll
        for (int w = 0; w < NT / 32; w++) s += red[w];
    }
    return s;
}

// ---- launch A: scale 0 (SSIM + pool -> g_p1) ----
__global__ void __launch_bounds__(NT, 5)
ssim_scale0(const float* __restrict__ A0, const float* __restrict__ B0)
{
    __shared__ __align__(16) float2 sSD[IH][LP];
    __shared__ __align__(16) ulonglong2 h12[IH][HP];
    __shared__ float red[NT / 32];

    const float G[11] = G_LIST;
    ull g2[11];
    #pragma unroll
    for (int k = 0; k < 11; k++) g2[k] = pack2(G[k], G[k]);

    const int tid   = threadIdx.x;
    const int tx    = blockIdx.x * TW;
    const int ty    = blockIdx.y * TH;
    const int plane = blockIdx.z;
    const int W = 512, H = 512;
    const size_t pbase = (size_t)plane * W * H;

    // stage 1: division-free map; 12 float4 slots/row, rows strided by 16
    {
        const int s  = tid & 15;      // slot, active if < 12
        const int r0 = tid >> 4;      // 0..15
        if (s < 12) {
            for (int r = r0; r < IH; r += 16) {
                int gy = ty + r - 5;
                int gx = tx + 4 * s - 8;
                float4 a = make_float4(0.f, 0.f, 0.f, 0.f);
                float4 b = a;
                if ((unsigned)gy < (unsigned)H && (unsigned)gx <= (unsigned)(W - 4)) {
                    size_t idx = pbase + (size_t)gy * W + gx;
                    a = *reinterpret_cast<const float4*>(A0 + idx);
                    b = *reinterpret_cast<const float4*>(B0 + idx);
                }
                float4 lo = make_float4(a.x + b.x, a.x - b.x, a.y + b.y, a.y - b.y);
                float4 hi = make_float4(a.z + b.z, a.z - b.z, a.w + b.w, a.w - b.w);
                *reinterpret_cast<float4*>(&sSD[r][4 * s])     = lo;
                *reinterpret_cast<float4*>(&sSD[r][4 * s + 2]) = hi;
            }
        }
    }
    __syncthreads();

    // stage 2 (threads < NGRP) concurrent with pool (threads >= NGRP)
    if (tid < NGRP) {
        h_group(sSD, h12, g2, tid);
    } else {
        for (int i = tid - NGRP; i < 256; i += NT - NGRP) {
            int pr = i >> 4;
            int pc = i & 15;
            int r = 5 + 2 * pr;
            int c = 8 + 2 * pc;
            float2 q00 = sSD[r][c],     q01 = sSD[r][c + 1];
            float2 q10 = sSD[r + 1][c], q11 = sSD[r + 1][c + 1];
            float2 o;
            o.x = 0.25f * (q00.x + q01.x + q10.x + q11.x);
            o.y = 0.25f * (q00.y + q01.y + q10.y + q11.y);
            size_t pidx = (size_t)plane * 256 * 256
                        + (size_t)((ty >> 1) + pr) * 256 + ((tx >> 1) + pc);
            g_p1[pidx] = o;
        }
    }
    __syncthreads();

    float s = v_pass_reduce(h12, red, g2);
    if (tid == 0) atomicAdd(&g_acc[0], s);
}

// ---- launch B: scales 1+2+3, all independent given g_p1 ----
__global__ void __launch_bounds__(NT, 5)
ssim_small(float* __restrict__ out)
{
    __shared__ __align__(16) float2 sSD[IH][LP];
    __shared__ __align__(16) ulonglong2 h12[IH][HP];
    __shared__ float red[NT / 32];

    const float G[11] = G_LIST;
    ull g2[11];
    #pragma unroll
    for (int k = 0; k < 11; k++) g2[k] = pack2(G[k], G[k]);

    const int bid = blockIdx.x;
    const int tid = threadIdx.x;

    int scale, plane, txi, tyi, W;
    if (bid < B_S1) {
        scale = 1; W = 256;
        plane = bid >> 6; int rem = bid & 63; tyi = rem >> 3; txi = rem & 7;
    } else if (bid < B_S1 + B_S2) {
        int r = bid - B_S1;
        scale = 2; W = 128;
        plane = r >> 4; int rem = r & 15; tyi = rem >> 2; txi = rem & 3;
    } else {
        int r = bid - (B_S1 + B_S2);
        scale = 3; W = 64;
        plane = r >> 2; int rem = r & 3; tyi = rem >> 1; txi = rem & 1;
    }
    const int H = W;
    const int tx = txi * TW;
    const int ty = tyi * TH;
    const size_t p1base = (size_t)plane * 256 * 256;
    const float2* __restrict__ P1 = g_p1;

    // ---- stage 1: build the scale-s (s,d) tile from g_p1 (division-free) ----
    if (scale == 1) {
        const int s  = tid & 31;      // float4 slot (2px), active if < 24
        const int r0 = tid >> 5;      // 0..7
        if (s < 24) {
            for (int r = r0; r < IH; r += 8) {
                int gy = ty + r - 5;
                int gx = tx + 2 * s - 8;
                float4 v = make_float4(0.f, 0.f, 0.f, 0.f);
                if ((unsigned)gy < 256u && (unsigned)gx <= 254u) {
                    v = *reinterpret_cast<const float4*>(P1 + p1base + (size_t)gy * 256 + gx);
                }
                *reinterpret_cast<float4*>(&sSD[r][2 * s]) = v;
            }
        }
    } else if (scale == 2) {
        const int c  = tid & 63;      // column, active if < 48
        const int r0 = tid >> 6;      // 0..3
        if (c < 48) {
            for (int r = r0; r < IH; r += 4) {
                int gy = ty + r - 5;
                int gx = tx + c - 8;
                float2 o = make_float2(0.f, 0.f);
                if ((unsigned)gy < (unsigned)H && (unsigned)gx < (unsigned)W) {
                    float4 r0v = *reinterpret_cast<const float4*>(
                        P1 + p1base + (size_t)(2 * gy) * 256 + 2 * gx);
                    float4 r1v = *reinterpret_cast<const float4*>(
                        P1 + p1base + (size_t)(2 * gy + 1) * 256 + 2 * gx);
                    o.x = 0.25f * (r0v.x + r0v.z + r1v.x + r1v.z);
                    o.y = 0.25f * (r0v.y + r0v.w + r1v.y + r1v.w);
                }
                sSD[r][c] = o;
            }
        }
    } else {
        const int c  = tid & 63;
        const int r0 = tid >> 6;
        if (c < 48) {
            for (int r = r0; r < IH; r += 4) {
                int gy = ty + r - 5;
                int gx = tx + c - 8;
                float2 o = make_float2(0.f, 0.f);
                if ((unsigned)gy < (unsigned)H && (unsigned)gx < (unsigned)W) {
                    float qx[4], qy[4];
                    #pragma unroll
                    for (int dy = 0; dy < 2; dy++) {
                        #pragma unroll
                        for (int dx = 0; dx < 2; dx++) {
                            int sy = 4 * gy + 2 * dy;
                            int sx = 4 * gx + 2 * dx;
                            float4 r0v = *reinterpret_cast<const float4*>(
                                P1 + p1base + (size_t)sy * 256 + sx);
                            float4 r1v = *reinterpret_cast<const float4*>(
                                P1 + p1base + (size_t)(sy + 1) * 256 + sx);
                            qx[2 * dy + dx] = 0.25f * (r0v.x + r0v.z + r1v.x + r1v.z);
                            qy[2 * dy + dx] = 0.25f * (r0v.y + r0v.w + r1v.y + r1v.w);
                        }
                    }
                    o.x = 0.25f * (qx[0] + qx[1] + qx[2] + qx[3]);
                    o.y = 0.25f * (qy[0] + qy[1] + qy[2] + qy[3]);
                }
                sSD[r][c] = o;
            }
        }
    }
    __syncthreads();

    if (tid < NGRP) h_group(sSD, h12, g2, tid);
    __syncthreads();

    float s = v_pass_reduce(h12, red, g2);
    if (tid == 0) {
        atomicAdd(&g_acc[scale], s);
        __threadfence();
        int d = atomicAdd(&g_fdone, 1);
        if (d == B_TOT - 1) {             // last block: finalize + reset
            float a0 = atomicAdd(&g_acc[0], 0.0f);
            float a1 = atomicAdd(&g_acc[1], 0.0f);
            float a2 = atomicAdd(&g_acc[2], 0.0f);
            float a3 = atomicAdd(&g_acc[3], 0.0f);
            const float wgt[4] = {0.0448f, 0.2856f, 0.3001f, 0.2363f};
            float n0 = 48.0f * 512.0f * 512.0f;
            out[0] = wgt[0] * (1.0f - a0 / n0)
                   + wgt[1] * (1.0f - a1 / (n0 * 0.25f))
                   + wgt[2] * (1.0f - a2 / (n0 * 0.0625f))
                   + wgt[3] * (1.0f - a3 / (n0 * 0.015625f));
            #pragma unroll
            for (int s4 = 0; s4 < 4; s4++) g_acc[s4] = 0.0f;
            g_fdone = 0;
        }
    }
}

extern "C" void kernel_launch(void* const* d_in, const int* in_sizes, int n_in,
                              void* d_out, int out_size) {
    const float* img1 = (const float*)d_in[0];
    const float* img2 = (const float*)d_in[1];
    float* out = (float*)d_out;

    ssim_scale0<<<dim3(16, 16, NPLANES), NT>>>(img1, img2);
    ssim_small<<<B_TOT, NT>>>(out);
}